// round 15
// baseline (speedup 1.0000x reference)
#include <cuda_runtime.h>

#define B 8
#define NPTS 2048
#define NPAIR (NPTS/2)
#define NTOT (B*NPTS)
#define LOGW 7.6246189861593985f   /* ln(2048) */
#define LOG2E 1.4426950408889634f
#define LN2 0.6931471805599453f
#define KSCALE8 32768.0f           /* 2^23 / 256 */
#define MAGICF 8388608.0f          /* 2^23 */
/* Schraudolph bias (127 - 0.043677)*2^23, pre-divided by 256, plus magic */
#define SCHB8 (1064986823.0f / 256.0f + 8388608.0f)

typedef unsigned long long u64;

__device__ float4 d_X4[NTOT];              // per-row coords (x,y,z, 0.5|p|^2)
__device__ float4 d_Y4[NTOT];
__device__ float4 d_cA[2][NTOT/2];         // pair-packed cols: (x0,x1,y0,y1)
__device__ float4 d_cB[2][NTOT/2];         // pair-packed cols: (z0,z1,-w0,-w1)
__device__ float d_pots[2][4][NTOT];       // [buffer][f,g,fx,gy][b*N+i]
__device__ float d_mprev[4][NTOT];         // row-max estimate (= w - softmin_raw)

__device__ __forceinline__ float lg2(float x){ float r; asm("lg2.approx.f32 %0, %1;":"=f"(r):"f"(x)); return r; }
__device__ __forceinline__ u64 dup2(float x){ u64 r; asm("mov.b64 %0, {%1, %1};":"=l"(r):"f"(x)); return r; }
__device__ __forceinline__ u64 pack2(float lo, float hi){ u64 r; asm("mov.b64 %0, {%1, %2};":"=l"(r):"f"(lo),"f"(hi)); return r; }
__device__ __forceinline__ u64 ffma2(u64 a, u64 b, u64 c){ u64 r; asm("fma.rn.f32x2 %0, %1, %2, %3;":"=l"(r):"l"(a),"l"(b),"l"(c)); return r; }
__device__ __forceinline__ u64 fadd2(u64 a, u64 b){ u64 r; asm("add.rn.f32x2 %0, %1, %2;":"=l"(r):"l"(a),"l"(b)); return r; }
__device__ __forceinline__ void unpk(u64 v, float& lo, float& hi){ asm("mov.b64 {%0, %1}, %2;":"=f"(lo),"=f"(hi):"l"(v)); }
__device__ __forceinline__ u64 ex2pair(u64 a){
    u64 r;
    asm("{\n\t.reg .f32 lo, hi, el, eh;\n\t"
        "mov.b64 {lo, hi}, %1;\n\t"
        "ex2.approx.ftz.f32 el, lo;\n\t"
        "ex2.approx.ftz.f32 eh, hi;\n\t"
        "mov.b64 %0, {el, eh};\n\t}"
        : "=l"(r) : "l"(a));
    return r;
}

__global__ void prep_kernel(const float* __restrict__ p1, const float* __restrict__ p2) {
    int i = blockIdx.x * blockDim.x + threadIdx.x;   // pair index
    if (i >= NTOT/2) return;
    int j0 = 2*i, j1 = 2*i + 1;
    float x0 = p1[3*j0], y0 = p1[3*j0+1], z0 = p1[3*j0+2];
    float x1 = p1[3*j1], y1 = p1[3*j1+1], z1 = p1[3*j1+2];
    float w0 = 0.5f*(x0*x0+y0*y0+z0*z0), w1 = 0.5f*(x1*x1+y1*y1+z1*z1);
    d_X4[j0] = make_float4(x0,y0,z0,w0);
    d_X4[j1] = make_float4(x1,y1,z1,w1);
    d_cA[0][i] = make_float4(x0,x1,y0,y1);
    d_cB[0][i] = make_float4(z0,z1,-w0,-w1);
    x0 = p2[3*j0]; y0 = p2[3*j0+1]; z0 = p2[3*j0+2];
    x1 = p2[3*j1]; y1 = p2[3*j1+1]; z1 = p2[3*j1+2];
    w0 = 0.5f*(x0*x0+y0*y0+z0*z0); w1 = 0.5f*(x1*x1+y1*y1+z1*z1);
    d_Y4[j0] = make_float4(x0,y0,z0,w0);
    d_Y4[j1] = make_float4(x1,y1,z1,w1);
    d_cA[1][i] = make_float4(x0,x1,y0,y1);
    d_cB[1][i] = make_float4(z0,z1,-w0,-w1);
    d_pots[0][0][j0]=0.f; d_pots[0][1][j0]=0.f; d_pots[0][2][j0]=0.f; d_pots[0][3][j0]=0.f;
    d_pots[0][0][j1]=0.f; d_pots[0][1][j1]=0.f; d_pots[0][2][j1]=0.f; d_pots[0][3][j1]=0.f;
    d_mprev[0][j0]=0.f; d_mprev[1][j0]=0.f; d_mprev[2][j0]=0.f; d_mprev[3][j0]=0.f;
    d_mprev[0][j1]=0.f; d_mprev[1][j1]=0.f; d_mprev[2][j1]=0.f; d_mprev[3][j1]=0.f;
}

#define RPW 4
#define WARPS 8
#define TPB (WARPS*32)  // 256
#define RPB (RPW*WARPS) // 32

// Single-pass softmin with prev-iteration max estimate.
//   softmin_i = 0.5|x_i|^2 - m - eps*ln( sum_j exp((t_ij - m)/eps) )
// exact=0: magic-splice Schraudolph exp — fma + alu only, ZERO XU/MUFU ops:
//   z = t*(kk*2^15) + (bias/256 + 2^23 - m*kk*2^15); z clamped to >= 2^23;
//   exp_bits = float_bits(z) << 8   (0x4B000000<<8 == 0 in 32 bits).
// exact=1: f32 MUFU exp (final extrapolation).
__global__ __launch_bounds__(TPB, 4) void iter_kernel(float eps, int inbuf, int avg, int exact) {
    __shared__ float4 shA[NPAIR];   // (x0,x1,y0,y1)
    __shared__ float4 shB[NPAIR];   // (z0,z1,w'0,w'1)
    int task = blockIdx.z, b = blockIdx.y;
    int ob = inbuf ^ 1;
    const float4* rows; const float4* cA; const float4* cB;
    const float* colpot; const float* rowold; float* outp;
    if (task == 0)      { rows = d_X4; cA = d_cA[1]; cB = d_cB[1]; colpot = d_pots[inbuf][1]; rowold = d_pots[inbuf][0]; outp = d_pots[ob][0]; }
    else if (task == 1) { rows = d_Y4; cA = d_cA[0]; cB = d_cB[0]; colpot = d_pots[inbuf][0]; rowold = d_pots[inbuf][1]; outp = d_pots[ob][1]; }
    else if (task == 2) { rows = d_X4; cA = d_cA[0]; cB = d_cB[0]; colpot = d_pots[inbuf][2]; rowold = d_pots[inbuf][2]; outp = d_pots[ob][2]; }
    else                { rows = d_Y4; cA = d_cA[1]; cB = d_cB[1]; colpot = d_pots[inbuf][3]; rowold = d_pots[inbuf][3]; outp = d_pots[ob][3]; }
    float* mprev = d_mprev[task] + b*NPTS;
    rows += b*NPTS; cA += b*NPAIR; cB += b*NPAIR; colpot += b*NPTS; rowold += b*NPTS; outp += b*NPTS;

    float eps_logw = eps * LOGW;
    for (int k = threadIdx.x; k < NPAIR; k += TPB) {
        shA[k] = cA[k];
        float4 zb = cB[k];
        float p0 = colpot[2*k], p1 = colpot[2*k+1];
        shB[k] = make_float4(zb.x, zb.y, p0 + zb.z - eps_logw, p1 + zb.w - eps_logw);
    }
    __syncthreads();

    int warp = threadIdx.x >> 5, lane = threadIdx.x & 31;
    int row0 = blockIdx.x * RPB + warp * RPW;

    float kk = LOG2E / eps;
    float kks8 = kk * KSCALE8;        // scale to (exponent-bit units)/256

    u64 rx2[RPW], ry2[RPW], rz2[RPW], mk2[RPW];
    u64 s2[RPW];
#pragma unroll
    for (int r = 0; r < RPW; r++) {
        float4 xr = rows[row0 + r];
        rx2[r] = dup2(xr.x); ry2[r] = dup2(xr.y); rz2[r] = dup2(xr.z);
        float me = mprev[row0 + r];
        mk2[r] = exact ? dup2(-me * kk) : dup2(SCHB8 - me * kks8);
        s2[r] = 0;
    }
    u64 kk2 = exact ? dup2(kk) : dup2(kks8);

    const ulonglong2* sA = (const ulonglong2*)shA;
    const ulonglong2* sB = (const ulonglong2*)shB;

    if (!exact) {
        // magic-splice path: fma + alu only, no XU
#pragma unroll 4
        for (int k = lane; k < NPAIR; k += 32) {
            ulonglong2 ab = sA[k];        // x-pair, y-pair
            ulonglong2 zw = sB[k];        // z-pair, w'-pair
#pragma unroll
            for (int r = 0; r < RPW; r++) {
                u64 t2 = ffma2(rz2[r], zw.x, zw.y);
                t2 = ffma2(ry2[r], ab.y, t2);
                t2 = ffma2(rx2[r], ab.x, t2);
                u64 z2 = ffma2(t2, kk2, mk2[r]);   // magic window [2^23, 2^24)
                float zl, zh; unpk(z2, zl, zh);
                zl = fmaxf(zl, MAGICF);            // underflow -> exact 0
                zh = fmaxf(zh, MAGICF);
                unsigned il = __float_as_uint(zl) << 8;
                unsigned ih = __float_as_uint(zh) << 8;
                s2[r] = fadd2(s2[r], pack2(__uint_as_float(il), __uint_as_float(ih)));
            }
        }
    } else {
        // exact f32 MUFU exp path (final extrapolation)
#pragma unroll 4
        for (int k = lane; k < NPAIR; k += 32) {
            ulonglong2 ab = sA[k];
            ulonglong2 zw = sB[k];
#pragma unroll
            for (int r = 0; r < RPW; r++) {
                u64 t2 = ffma2(rz2[r], zw.x, zw.y);
                t2 = ffma2(ry2[r], ab.y, t2);
                t2 = ffma2(rx2[r], ab.x, t2);
                s2[r] = fadd2(s2[r], ex2pair(ffma2(t2, kk2, mk2[r])));
            }
        }
    }

    float s[RPW];
#pragma unroll
    for (int r = 0; r < RPW; r++) { float lo, hi; unpk(s2[r], lo, hi); s[r] = lo + hi; }
#pragma unroll
    for (int off = 16; off; off >>= 1)
#pragma unroll
        for (int r = 0; r < RPW; r++)
            s[r] += __shfl_xor_sync(0xffffffffu, s[r], off);

    float m_used[RPW];
#pragma unroll
    for (int r = 0; r < RPW; r++) m_used[r] = mprev[row0 + r];

    float kkx = LOG2E / eps;
    // safety net: NaN/negative/overflow/underflow in s -> exact recompute
    unsigned badmask = 0;
#pragma unroll
    for (int r = 0; r < RPW; r++)
        if (!(s[r] >= 1e-12f && s[r] <= 1e30f)) badmask |= 1u << r;
    if (__any_sync(0xffffffffu, badmask != 0)) {
        u64 kkb = dup2(kkx);
        float mlo[RPW], mhi[RPW];
#pragma unroll
        for (int r = 0; r < RPW; r++) { mlo[r] = -3.4e38f; mhi[r] = -3.4e38f; }
        for (int k = lane; k < NPAIR; k += 32) {
            ulonglong2 ab = sA[k];
            ulonglong2 zw = sB[k];
#pragma unroll
            for (int r = 0; r < RPW; r++) {
                u64 t2 = ffma2(rz2[r], zw.x, zw.y);
                t2 = ffma2(ry2[r], ab.y, t2);
                t2 = ffma2(rx2[r], ab.x, t2);
                float lo, hi; unpk(t2, lo, hi);
                mlo[r] = fmaxf(mlo[r], lo);
                mhi[r] = fmaxf(mhi[r], hi);
            }
        }
        float mt[RPW];
#pragma unroll
        for (int r = 0; r < RPW; r++) mt[r] = fmaxf(mlo[r], mhi[r]);
#pragma unroll
        for (int off = 16; off; off >>= 1)
#pragma unroll
            for (int r = 0; r < RPW; r++)
                mt[r] = fmaxf(mt[r], __shfl_xor_sync(0xffffffffu, mt[r], off));
        u64 sb2[RPW], mkb[RPW];
#pragma unroll
        for (int r = 0; r < RPW; r++) { mkb[r] = dup2(-mt[r] * kkx); sb2[r] = 0; }
        for (int k = lane; k < NPAIR; k += 32) {
            ulonglong2 ab = sA[k];
            ulonglong2 zw = sB[k];
#pragma unroll
            for (int r = 0; r < RPW; r++) {
                u64 t2 = ffma2(rz2[r], zw.x, zw.y);
                t2 = ffma2(ry2[r], ab.y, t2);
                t2 = ffma2(rx2[r], ab.x, t2);
                sb2[r] = fadd2(sb2[r], ex2pair(ffma2(t2, kkb, mkb[r])));
            }
        }
        float sn[RPW];
#pragma unroll
        for (int r = 0; r < RPW; r++) { float lo, hi; unpk(sb2[r], lo, hi); sn[r] = lo + hi; }
#pragma unroll
        for (int off = 16; off; off >>= 1)
#pragma unroll
            for (int r = 0; r < RPW; r++)
                sn[r] += __shfl_xor_sync(0xffffffffu, sn[r], off);
#pragma unroll
        for (int r = 0; r < RPW; r++)
            if ((badmask >> r) & 1u) { s[r] = sn[r]; m_used[r] = mt[r]; }
    }

    if (lane < RPW) {
        int r = lane;
        int row = row0 + r;
        float rww = rows[row].w;
        float sm = rww - m_used[r] - eps * (lg2(s[r]) * LN2);
        outp[row] = avg ? 0.5f * (rowold[row] + sm) : sm;
        mprev[row] = rww - sm;
    }
}

__global__ void reduce_kernel(int buf, float* __restrict__ out) {
    __shared__ float red[256];
    float acc = 0.f;
    for (int i = threadIdx.x; i < NTOT; i += 256) {
        acc += (d_pots[buf][0][i] - d_pots[buf][2][i])
             + (d_pots[buf][1][i] - d_pots[buf][3][i]);
    }
    red[threadIdx.x] = acc;
    __syncthreads();
    for (int off = 128; off; off >>= 1) {
        if (threadIdx.x < off) red[threadIdx.x] += red[threadIdx.x + off];
        __syncthreads();
    }
    if (threadIdx.x == 0) out[0] = red[0] / (float)NTOT;
}

extern "C" void kernel_launch(void* const* d_in, const int* in_sizes, int n_in,
                              void* d_out, int out_size) {
    const float* p1 = (const float*)d_in[0];
    const float* p2 = (const float*)d_in[1];
    float* out = (float*)d_out;

    float eps[128]; int n = 0;
    double sc = 8.0;
    while (sc > 0.01 && n < 120) { float f = (float)sc; eps[n++] = f * f; sc *= 0.9; }
    { float f = 0.01f; eps[n++] = f * f; }

    prep_kernel<<<(NTOT/2 + 255) / 256, 256>>>(p1, p2);

    int inbuf = 0;
    dim3 grid(NPTS / RPB, B, 4);
    for (int k = 0; k < n; k++) {
        iter_kernel<<<grid, TPB>>>(eps[k], inbuf, 1, 0);
        inbuf ^= 1;
    }
    // final extrapolation at target eps: exact f32 exp, no averaging
    iter_kernel<<<grid, TPB>>>(eps[n - 1], inbuf, 0, 1);
    reduce_kernel<<<1, 256>>>(inbuf ^ 1, out);
}

// round 17
// speedup vs baseline: 1.3459x; 1.3459x over previous
#include <cuda_runtime.h>
#include <cuda_fp16.h>

#define B 8
#define NPTS 2048
#define NPAIR (NPTS/2)
#define NTOT (B*NPTS)
#define LOGW 7.6246189861593985f   /* ln(2048) */
#define LOG2E 1.4426950408889634f
#define LN2 0.6931471805599453f

typedef unsigned long long u64;

__device__ float4 d_X4[NTOT];              // per-row coords (x,y,z, 0.5|p|^2)
__device__ float4 d_Y4[NTOT];
__device__ float4 d_cA[2][NTOT/2];         // pair-packed cols: (x0,x1,y0,y1)
__device__ float4 d_cB[2][NTOT/2];         // pair-packed cols: (z0,z1,-w0,-w1)
__device__ float d_pots[2][4][NTOT];       // [buffer][f,g,fx,gy][b*N+i]
__device__ float d_mprev[4][NTOT];         // row-max estimate (= w - softmin_raw)

__device__ __forceinline__ float lg2(float x){ float r; asm("lg2.approx.f32 %0, %1;":"=f"(r):"f"(x)); return r; }
__device__ __forceinline__ u64 dup2(float x){ u64 r; asm("mov.b64 %0, {%1, %1};":"=l"(r):"f"(x)); return r; }
__device__ __forceinline__ u64 ffma2(u64 a, u64 b, u64 c){ u64 r; asm("fma.rn.f32x2 %0, %1, %2, %3;":"=l"(r):"l"(a),"l"(b),"l"(c)); return r; }
__device__ __forceinline__ u64 fadd2(u64 a, u64 b){ u64 r; asm("add.rn.f32x2 %0, %1, %2;":"=l"(r):"l"(a),"l"(b)); return r; }
__device__ __forceinline__ void unpk(u64 v, float& lo, float& hi){ asm("mov.b64 {%0, %1}, %2;":"=f"(lo),"=f"(hi):"l"(v)); }
// f32x2 (packed) -> f16x2 -> packed exp2: ONE issue for two exponentials
__device__ __forceinline__ unsigned ex2h2(u64 u2){
    unsigned r;
    asm("{\n\t.reg .f32 lo, hi;\n\t.reg .b32 h;\n\t"
        "mov.b64 {lo, hi}, %1;\n\t"
        "cvt.rn.f16x2.f32 h, hi, lo;\n\t"
        "ex2.approx.f16x2 %0, h;\n\t}"
        : "=r"(r) : "l"(u2));
    return r;
}
__device__ __forceinline__ unsigned hadd2(unsigned a, unsigned b){
    unsigned r; asm("add.rn.f16x2 %0, %1, %2;":"=r"(r):"r"(a),"r"(b)); return r;
}
__device__ __forceinline__ u64 ex2pair(u64 a){
    u64 r;
    asm("{\n\t.reg .f32 lo, hi, el, eh;\n\t"
        "mov.b64 {lo, hi}, %1;\n\t"
        "ex2.approx.ftz.f32 el, lo;\n\t"
        "ex2.approx.ftz.f32 eh, hi;\n\t"
        "mov.b64 %0, {el, eh};\n\t}"
        : "=l"(r) : "l"(a));
    return r;
}

__global__ void prep_kernel(const float* __restrict__ p1, const float* __restrict__ p2) {
    int i = blockIdx.x * blockDim.x + threadIdx.x;   // pair index
    if (i >= NTOT/2) return;
    int j0 = 2*i, j1 = 2*i + 1;
    float x0 = p1[3*j0], y0 = p1[3*j0+1], z0 = p1[3*j0+2];
    float x1 = p1[3*j1], y1 = p1[3*j1+1], z1 = p1[3*j1+2];
    float w0 = 0.5f*(x0*x0+y0*y0+z0*z0), w1 = 0.5f*(x1*x1+y1*y1+z1*z1);
    d_X4[j0] = make_float4(x0,y0,z0,w0);
    d_X4[j1] = make_float4(x1,y1,z1,w1);
    d_cA[0][i] = make_float4(x0,x1,y0,y1);
    d_cB[0][i] = make_float4(z0,z1,-w0,-w1);
    x0 = p2[3*j0]; y0 = p2[3*j0+1]; z0 = p2[3*j0+2];
    x1 = p2[3*j1]; y1 = p2[3*j1+1]; z1 = p2[3*j1+2];
    w0 = 0.5f*(x0*x0+y0*y0+z0*z0); w1 = 0.5f*(x1*x1+y1*y1+z1*z1);
    d_Y4[j0] = make_float4(x0,y0,z0,w0);
    d_Y4[j1] = make_float4(x1,y1,z1,w1);
    d_cA[1][i] = make_float4(x0,x1,y0,y1);
    d_cB[1][i] = make_float4(z0,z1,-w0,-w1);
    d_pots[0][0][j0]=0.f; d_pots[0][1][j0]=0.f; d_pots[0][2][j0]=0.f; d_pots[0][3][j0]=0.f;
    d_pots[0][0][j1]=0.f; d_pots[0][1][j1]=0.f; d_pots[0][2][j1]=0.f; d_pots[0][3][j1]=0.f;
    d_mprev[0][j0]=0.f; d_mprev[1][j0]=0.f; d_mprev[2][j0]=0.f; d_mprev[3][j0]=0.f;
    d_mprev[0][j1]=0.f; d_mprev[1][j1]=0.f; d_mprev[2][j1]=0.f; d_mprev[3][j1]=0.f;
}

#define RPW 4
#define WARPS 8
#define TPB (WARPS*32)  // 256
#define RPB (RPW*WARPS) // 32

// Single-pass softmin with prev-iteration max estimate (R10 body, unchanged).
__global__ __launch_bounds__(TPB, 4) void iter_kernel(float eps, int inbuf, int avg, int exact) {
    __shared__ float4 shA[NPAIR];   // (x0,x1,y0,y1)
    __shared__ float4 shB[NPAIR];   // (z0,z1,w'0,w'1)
    int task = blockIdx.z, b = blockIdx.y;
    int ob = inbuf ^ 1;
    const float4* rows; const float4* cA; const float4* cB;
    const float* colpot; const float* rowold; float* outp;
    if (task == 0)      { rows = d_X4; cA = d_cA[1]; cB = d_cB[1]; colpot = d_pots[inbuf][1]; rowold = d_pots[inbuf][0]; outp = d_pots[ob][0]; }
    else if (task == 1) { rows = d_Y4; cA = d_cA[0]; cB = d_cB[0]; colpot = d_pots[inbuf][0]; rowold = d_pots[inbuf][1]; outp = d_pots[ob][1]; }
    else if (task == 2) { rows = d_X4; cA = d_cA[0]; cB = d_cB[0]; colpot = d_pots[inbuf][2]; rowold = d_pots[inbuf][2]; outp = d_pots[ob][2]; }
    else                { rows = d_Y4; cA = d_cA[1]; cB = d_cB[1]; colpot = d_pots[inbuf][3]; rowold = d_pots[inbuf][3]; outp = d_pots[ob][3]; }
    float* mprev = d_mprev[task] + b*NPTS;
    rows += b*NPTS; cA += b*NPAIR; cB += b*NPAIR; colpot += b*NPTS; rowold += b*NPTS; outp += b*NPTS;

    float eps_logw = eps * LOGW;
    for (int k = threadIdx.x; k < NPAIR; k += TPB) {
        shA[k] = cA[k];
        float4 zb = cB[k];
        float p0 = colpot[2*k], p1 = colpot[2*k+1];
        shB[k] = make_float4(zb.x, zb.y, p0 + zb.z - eps_logw, p1 + zb.w - eps_logw);
    }
    __syncthreads();

    int warp = threadIdx.x >> 5, lane = threadIdx.x & 31;
    int row0 = blockIdx.x * RPB + warp * RPW;

    float kk = LOG2E / eps;
    u64 kk2 = dup2(kk);

    u64 rx2[RPW], ry2[RPW], rz2[RPW], mk2[RPW];
    float slo[RPW], shi[RPW];
#pragma unroll
    for (int r = 0; r < RPW; r++) {
        float4 xr = rows[row0 + r];
        rx2[r] = dup2(xr.x); ry2[r] = dup2(xr.y); rz2[r] = dup2(xr.z);
        mk2[r] = dup2(-mprev[row0 + r] * kk);
        slo[r] = 0.f; shi[r] = 0.f;
    }

    const ulonglong2* sA = (const ulonglong2*)shA;
    const ulonglong2* sB = (const ulonglong2*)shB;

    if (!exact) {
        // f16x2 exp path: chunks of 8 lane-steps per f16x2 accumulator
#pragma unroll 1
        for (int kb = 0; kb < NPAIR; kb += 256) {
            unsigned hacc[RPW];
#pragma unroll
            for (int r = 0; r < RPW; r++) hacc[r] = 0u;
#pragma unroll
            for (int kc = 0; kc < 8; kc++) {
                int k = kb + kc * 32 + lane;
                ulonglong2 ab = sA[k];        // x-pair, y-pair
                ulonglong2 zw = sB[k];        // z-pair, w'-pair
#pragma unroll
                for (int r = 0; r < RPW; r++) {
                    u64 t2 = ffma2(rz2[r], zw.x, zw.y);
                    t2 = ffma2(ry2[r], ab.y, t2);
                    t2 = ffma2(rx2[r], ab.x, t2);
                    u64 u2 = ffma2(t2, kk2, mk2[r]);
                    hacc[r] = hadd2(hacc[r], ex2h2(u2));
                }
            }
#pragma unroll
            for (int r = 0; r < RPW; r++) {
                float2 f = __half22float2(*(const __half2*)&hacc[r]);
                slo[r] += f.x; shi[r] += f.y;
            }
        }
    } else {
        // exact f32 exp path (final extrapolation)
#pragma unroll 4
        for (int k = lane; k < NPAIR; k += 32) {
            ulonglong2 ab = sA[k];
            ulonglong2 zw = sB[k];
#pragma unroll
            for (int r = 0; r < RPW; r++) {
                u64 t2 = ffma2(rz2[r], zw.x, zw.y);
                t2 = ffma2(ry2[r], ab.y, t2);
                t2 = ffma2(rx2[r], ab.x, t2);
                u64 u2 = ffma2(t2, kk2, mk2[r]);
                u64 e2 = ex2pair(u2);
                float lo, hi; unpk(e2, lo, hi);
                slo[r] += lo; shi[r] += hi;
            }
        }
    }

    float s[RPW];
#pragma unroll
    for (int r = 0; r < RPW; r++) s[r] = slo[r] + shi[r];
#pragma unroll
    for (int off = 16; off; off >>= 1)
#pragma unroll
        for (int r = 0; r < RPW; r++)
            s[r] += __shfl_xor_sync(0xffffffffu, s[r], off);

    // reload cross-loop values instead of keeping them live through the loop
    float m_used[RPW];
#pragma unroll
    for (int r = 0; r < RPW; r++) m_used[r] = mprev[row0 + r];

    // safety net: if max estimate was too far off, recompute max + resum (cold)
    unsigned badmask = 0;
#pragma unroll
    for (int r = 0; r < RPW; r++)
        if (!(s[r] >= 1e-12f && s[r] <= 1e30f)) badmask |= 1u << r;
    if (__any_sync(0xffffffffu, badmask != 0)) {
        float mlo[RPW], mhi[RPW];
#pragma unroll
        for (int r = 0; r < RPW; r++) { mlo[r] = -3.4e38f; mhi[r] = -3.4e38f; }
        for (int k = lane; k < NPAIR; k += 32) {
            ulonglong2 ab = sA[k];
            ulonglong2 zw = sB[k];
#pragma unroll
            for (int r = 0; r < RPW; r++) {
                u64 t2 = ffma2(rz2[r], zw.x, zw.y);
                t2 = ffma2(ry2[r], ab.y, t2);
                t2 = ffma2(rx2[r], ab.x, t2);
                float lo, hi; unpk(t2, lo, hi);
                mlo[r] = fmaxf(mlo[r], lo);
                mhi[r] = fmaxf(mhi[r], hi);
            }
        }
        float mt[RPW];
#pragma unroll
        for (int r = 0; r < RPW; r++) mt[r] = fmaxf(mlo[r], mhi[r]);
#pragma unroll
        for (int off = 16; off; off >>= 1)
#pragma unroll
            for (int r = 0; r < RPW; r++)
                mt[r] = fmaxf(mt[r], __shfl_xor_sync(0xffffffffu, mt[r], off));
        u64 sb2[RPW], mkb[RPW];
#pragma unroll
        for (int r = 0; r < RPW; r++) { mkb[r] = dup2(-mt[r] * kk); sb2[r] = 0; }
        for (int k = lane; k < NPAIR; k += 32) {
            ulonglong2 ab = sA[k];
            ulonglong2 zw = sB[k];
#pragma unroll
            for (int r = 0; r < RPW; r++) {
                u64 t2 = ffma2(rz2[r], zw.x, zw.y);
                t2 = ffma2(ry2[r], ab.y, t2);
                t2 = ffma2(rx2[r], ab.x, t2);
                u64 u2 = ffma2(t2, kk2, mkb[r]);
                sb2[r] = fadd2(sb2[r], ex2pair(u2));
            }
        }
        float sn[RPW];
#pragma unroll
        for (int r = 0; r < RPW; r++) { float lo, hi; unpk(sb2[r], lo, hi); sn[r] = lo + hi; }
#pragma unroll
        for (int off = 16; off; off >>= 1)
#pragma unroll
            for (int r = 0; r < RPW; r++)
                sn[r] += __shfl_xor_sync(0xffffffffu, sn[r], off);
#pragma unroll
        for (int r = 0; r < RPW; r++)
            if ((badmask >> r) & 1u) { s[r] = sn[r]; m_used[r] = mt[r]; }
    }

    if (lane < RPW) {
        int r = lane;
        int row = row0 + r;
        float rww = rows[row].w;   // reload (kept out of hot-loop liveness)
        float sm = rww - m_used[r] - eps * (lg2(s[r]) * LN2);
        outp[row] = avg ? 0.5f * (rowold[row] + sm) : sm;
        mprev[row] = rww - sm;     // = m_used + eps*ln(s): next iter's max estimate
    }
}

__global__ void reduce_kernel(int buf, float* __restrict__ out) {
    __shared__ float red[256];
    float acc = 0.f;
    for (int i = threadIdx.x; i < NTOT; i += 256) {
        acc += (d_pots[buf][0][i] - d_pots[buf][2][i])
             + (d_pots[buf][1][i] - d_pots[buf][3][i]);
    }
    red[threadIdx.x] = acc;
    __syncthreads();
    for (int off = 128; off; off >>= 1) {
        if (threadIdx.x < off) red[threadIdx.x] += red[threadIdx.x + off];
        __syncthreads();
    }
    if (threadIdx.x == 0) out[0] = red[0] / (float)NTOT;
}

extern "C" void kernel_launch(void* const* d_in, const int* in_sizes, int n_in,
                              void* d_out, int out_size) {
    const float* p1 = (const float*)d_in[0];
    const float* p2 = (const float*)d_in[1];
    float* out = (float*)d_out;

    // epsilon schedule: anneal in f64 (python-float semantics), square in f32.
    // THINNED only in the strongly-contracting region: skip every other level
    // while sc >= 2.0 (eps >= 4.1). All levels below sc=2 are EXACT — R16
    // showed skips near eps<4 leak through the weakly-contracting low-eps
    // phase; skips at eps>=4 are erased by the intact [0.5,4] band.
    float eps[128]; int n = 0;
    double sc = 8.0; int j = 0;
    while (sc > 0.01 && n < 120) {
        if (!(sc >= 2.0 && (j & 1))) { float f = (float)sc; eps[n++] = f * f; }
        sc *= 0.9; j++;
    }
    { float f = 0.01f; eps[n++] = f * f; }

    prep_kernel<<<(NTOT/2 + 255) / 256, 256>>>(p1, p2);

    int inbuf = 0;
    dim3 grid(NPTS / RPB, B, 4);
    for (int k = 0; k < n; k++) {
        iter_kernel<<<grid, TPB>>>(eps[k], inbuf, 1, 0);
        inbuf ^= 1;
    }
    // final extrapolation at target eps: exact f32 exp, no averaging
    iter_kernel<<<grid, TPB>>>(eps[n - 1], inbuf, 0, 1);
    reduce_kernel<<<1, 256>>>(inbuf ^ 1, out);
}